// round 1
// baseline (speedup 1.0000x reference)
#include <cuda_runtime.h>

// Problem shape constants (fixed by setup_inputs)
#define NE_C 100000
#define NR_C 1000
#define DD   128
#define UU   128
#define E_C  500000

// Scratch (allocation-free: __device__ globals)
__device__ float g_EW1[NE_C * UU];     // entity_emb @ W1
__device__ float g_EW3[NE_C * UU];     // entity_emb @ W3
__device__ float g_RW2[NR_C * UU];     // relation_emb @ W2
__device__ float g_sA[NE_C];           // entity_emb @ (W1 @ a)
__device__ float g_sB[NE_C];           // entity_emb @ (W3 @ a)
__device__ float g_sR[NR_C];           // relation_emb @ (W2 @ a) + a_b
__device__ float g_wa[3 * DD];         // W @ a  (384 values)
__device__ float g_escore[E_C];        // exp(score) per edge
__device__ float g_denom[NE_C];        // segment sum of exp(score)

// ---------------------------------------------------------------------------
// K0: zero output + denom
__global__ void k_init(float* __restrict__ out, int ne) {
    int idx = blockIdx.x * blockDim.x + threadIdx.x;
    if (idx < ne * UU) out[idx] = 0.0f;
    if (idx < ne) g_denom[idx] = 0.0f;
}

// ---------------------------------------------------------------------------
// K1: wa[k] = W[k,:] . a   for k in [0,384)
__global__ void k_wa(const float* __restrict__ W, const float* __restrict__ a) {
    int k = threadIdx.x;  // 384 threads
    const float* row = W + k * UU;
    float acc = 0.0f;
#pragma unroll 8
    for (int u = 0; u < UU; u++) acc += row[u] * a[u];
    g_wa[k] = acc;
}

// ---------------------------------------------------------------------------
// K2: RW2[j,:] = R[j,:] @ W2 ; sR[j] = R[j,:] . wa2 + a_b   (block per relation)
__global__ void k_rw2(const float* __restrict__ R, const float* __restrict__ W,
                      const float* __restrict__ a_b) {
    __shared__ float r_sh[DD];
    __shared__ float red[4];
    int j = blockIdx.x;
    int u = threadIdx.x;  // 128 threads
    r_sh[u] = R[j * DD + u];
    __syncthreads();
    float acc = 0.0f;
    const float* Wp = W + 128 * UU + u;  // W2 rows start at 128
#pragma unroll 8
    for (int k = 0; k < DD; k++) acc += r_sh[k] * Wp[k * UU];
    g_RW2[j * UU + u] = acc;
    // sR reduction
    float p = r_sh[u] * g_wa[128 + u];
#pragma unroll
    for (int o = 16; o > 0; o >>= 1) p += __shfl_down_sync(0xffffffffu, p, o);
    if ((u & 31) == 0) red[u >> 5] = p;
    __syncthreads();
    if (u == 0) g_sR[j] = red[0] + red[1] + red[2] + red[3] + a_b[0];
}

// ---------------------------------------------------------------------------
// K3: sA[n] = E[n,:] . wa1 ; sB[n] = E[n,:] . wa3   (warp per entity row)
__global__ void k_s(const float* __restrict__ Eemb, int ne) {
    int warp = (blockIdx.x * blockDim.x + threadIdx.x) >> 5;
    int lane = threadIdx.x & 31;
    if (warp >= ne) return;
    float4 v  = ((const float4*)(Eemb + (size_t)warp * DD))[lane];
    float4 w1 = ((const float4*)(g_wa))[lane];
    float4 w3 = ((const float4*)(g_wa + 256))[lane];
    float pa = v.x * w1.x + v.y * w1.y + v.z * w1.z + v.w * w1.w;
    float pb = v.x * w3.x + v.y * w3.y + v.z * w3.z + v.w * w3.w;
#pragma unroll
    for (int o = 16; o > 0; o >>= 1) {
        pa += __shfl_xor_sync(0xffffffffu, pa, o);
        pb += __shfl_xor_sync(0xffffffffu, pb, o);
    }
    if (lane == 0) { g_sA[warp] = pa; g_sB[warp] = pb; }
}

// ---------------------------------------------------------------------------
// K4: big GEMM — C[ne x 256] = Eemb[ne x 128] @ [W1 | W3], split into EW1/EW3.
// 64-row tile per block, 256 threads, 8x8 register tile per thread.
#define GEMM_BM 64
#define GEMM_SMEM ((GEMM_BM * DD + DD * 256) * 4)   // 32KB A + 128KB W = 160KB
__global__ void __launch_bounds__(256, 1)
k_gemm(const float* __restrict__ Eemb, const float* __restrict__ W, int ne) {
    extern __shared__ float sm[];
    float* Ash = sm;                 // [64][128]
    float* Wsh = sm + GEMM_BM * DD;  // [128][256]  (cols 0..127 = W1, 128..255 = W3)
    int tid = threadIdx.x;
    int row0 = blockIdx.x * GEMM_BM;

    // Load W halves: Wsh[k][half*128 + col] = W[(k + half*256)*128 + col]
#pragma unroll
    for (int it = 0; it < 32; it++) {
        int e = it * 1024 + tid * 4;
        int col  = e & 127;
        int k    = (e >> 7) & 127;
        int half = e >> 14;
        float4 w = *(const float4*)(W + (size_t)(k + (half ? 256 : 0)) * UU + col);
        *(float4*)(Wsh + k * 256 + half * 128 + col) = w;
    }
    // Load A tile (zero-pad rows past ne)
#pragma unroll
    for (int it = 0; it < 8; it++) {
        int e = it * 1024 + tid * 4;
        int r = e >> 7;
        int c = e & 127;
        float4 v = make_float4(0.f, 0.f, 0.f, 0.f);
        if (row0 + r < ne) v = *(const float4*)(Eemb + (size_t)(row0 + r) * DD + c);
        *(float4*)(Ash + r * DD + c) = v;
    }
    __syncthreads();

    int tn = tid & 31;   // col group: cols tn*8 .. tn*8+7
    int tm = tid >> 5;   // row group: rows tm*8 .. tm*8+7 (warp-uniform -> A broadcast)
    float acc[8][8];
#pragma unroll
    for (int i = 0; i < 8; i++)
#pragma unroll
        for (int j = 0; j < 8; j++) acc[i][j] = 0.f;

    const float* Ap = Ash + (tm * 8) * DD;
    const float* Wp = Wsh + tn * 8;
#pragma unroll 2
    for (int k = 0; k < DD; k++) {
        float a0[8];
#pragma unroll
        for (int i = 0; i < 8; i++) a0[i] = Ap[i * DD + k];
        float4 b0 = *(const float4*)(Wp + k * 256);
        float4 b1 = *(const float4*)(Wp + k * 256 + 4);
        float b[8] = {b0.x, b0.y, b0.z, b0.w, b1.x, b1.y, b1.z, b1.w};
#pragma unroll
        for (int i = 0; i < 8; i++)
#pragma unroll
            for (int j = 0; j < 8; j++) acc[i][j] += a0[i] * b[j];
    }

    int c0 = tn * 8;
#pragma unroll
    for (int i = 0; i < 8; i++) {
        int row = row0 + tm * 8 + i;
        if (row < ne) {
            float* dst = (c0 < 128) ? (g_EW1 + (size_t)row * UU + c0)
                                    : (g_EW3 + (size_t)row * UU + (c0 - 128));
            *(float4*)(dst)     = make_float4(acc[i][0], acc[i][1], acc[i][2], acc[i][3]);
            *(float4*)(dst + 4) = make_float4(acc[i][4], acc[i][5], acc[i][6], acc[i][7]);
        }
    }
}

// ---------------------------------------------------------------------------
// K5: per-edge score -> exp -> segment denom.  score = leaky(leaky(sA+sR+sB))
__global__ void k_edge1(const int* __restrict__ h, const int* __restrict__ r,
                        const int* __restrict__ t, int E) {
    int e = blockIdx.x * blockDim.x + threadIdx.x;
    if (e >= E) return;
    float s = g_sA[h[e]] + g_sR[r[e]] + g_sB[t[e]];
    float sc = (s >= 0.f) ? s : 0.04f * s;   // leaky(leaky(x)), alpha=0.2
    float es = expf(sc);                     // no max-shift needed (|score| small)
    g_escore[e] = es;
    atomicAdd(&g_denom[h[e]], es);
}

// ---------------------------------------------------------------------------
// K6: per-edge aggregate: out[h] += alpha * (RW2[r] + EW3[t])   (warp per edge)
__global__ void k_edge2(const int* __restrict__ h, const int* __restrict__ r,
                        const int* __restrict__ t, float* __restrict__ out, int E) {
    int warp = (blockIdx.x * blockDim.x + threadIdx.x) >> 5;
    int lane = threadIdx.x & 31;
    if (warp >= E) return;
    int hn = h[warp], rn = r[warp], tn = t[warp];
    float alpha = g_escore[warp] / g_denom[hn];
    float4 rv = ((const float4*)(g_RW2 + (size_t)rn * UU))[lane];
    float4 tv = ((const float4*)(g_EW3 + (size_t)tn * UU))[lane];
    float4 val = make_float4(alpha * (rv.x + tv.x), alpha * (rv.y + tv.y),
                             alpha * (rv.z + tv.z), alpha * (rv.w + tv.w));
    atomicAdd(((float4*)(out + (size_t)hn * UU)) + lane, val);  // RED.128, sm_90+
}

// ---------------------------------------------------------------------------
// K7: out = relu(out + [denom>0]*EW1 + bias)   (softmax weights sum to 1 ->
// the alpha-weighted EW1[h] contribution is exactly EW1[n] per nonempty segment)
__global__ void k_final(float* __restrict__ out, const float* __restrict__ bias, int ne) {
    int idx = blockIdx.x * blockDim.x + threadIdx.x;
    if (idx >= ne * UU) return;
    int n = idx >> 7;
    int u = idx & 127;
    float v = out[idx] + bias[u];
    if (g_denom[n] > 0.f) v += g_EW1[idx];
    out[idx] = fmaxf(v, 0.f);
}

// ---------------------------------------------------------------------------
extern "C" void kernel_launch(void* const* d_in, const int* in_sizes, int n_in,
                              void* d_out, int out_size) {
    const int*   h    = (const int*)d_in[0];
    const int*   r    = (const int*)d_in[1];
    const int*   t    = (const int*)d_in[2];
    const float* Eemb = (const float*)d_in[3];
    const float* Remb = (const float*)d_in[4];
    const float* W    = (const float*)d_in[5];
    const float* a    = (const float*)d_in[6];
    const float* ab   = (const float*)d_in[7];
    const float* bias = (const float*)d_in[8];
    float* out = (float*)d_out;

    int E  = in_sizes[0];
    int ne = in_sizes[3] / DD;
    int nr = in_sizes[4] / DD;

    cudaFuncSetAttribute(k_gemm, cudaFuncAttributeMaxDynamicSharedMemorySize, GEMM_SMEM);

    k_init  <<<(ne * UU + 255) / 256, 256>>>(out, ne);
    k_wa    <<<1, 384>>>(W, a);
    k_rw2   <<<nr, 128>>>(Remb, W, ab);
    k_s     <<<(ne + 7) / 8, 256>>>(Eemb, ne);
    k_gemm  <<<(ne + GEMM_BM - 1) / GEMM_BM, 256, GEMM_SMEM>>>(Eemb, W, ne);
    k_edge1 <<<(E + 255) / 256, 256>>>(h, r, t, E);
    k_edge2 <<<(E + 7) / 8, 256>>>(h, r, t, out, E);
    k_final <<<(ne * UU + 255) / 256, 256>>>(out, bias, ne);
}

// round 3
// speedup vs baseline: 1.4076x; 1.4076x over previous
#include <cuda_runtime.h>
#include <cuda_bf16.h>

#define NE_C 100000
#define NR_C 1000
#define DD   128
#define UU   128
#define E_C  500000

// ---------------- scratch (__device__ globals, allocation-free) ----------------
__device__ float g_EW1[NE_C * UU];
__device__ float g_EW3[NE_C * UU];
__device__ float g_RW2[NR_C * UU];
__device__ float g_sA[NE_C];
__device__ float g_sB[NE_C];
__device__ float g_sR[NR_C];
__device__ float g_escore[E_C];
__device__ float g_denom[NE_C];

// ---------------------------------------------------------------------------
// K0: zero output + denom
__global__ void k_init(float* __restrict__ out, int ne) {
    int idx = blockIdx.x * blockDim.x + threadIdx.x;
    if (idx < ne * UU) out[idx] = 0.0f;
    if (idx < ne) g_denom[idx] = 0.0f;
}

// K2: RW2[j,:] = R[j,:] @ W2 ; sR[j] = RW2[j,:] . a + a_b   (block per relation)
__global__ void k_rw2(const float* __restrict__ R, const float* __restrict__ W,
                      const float* __restrict__ a, const float* __restrict__ a_b) {
    __shared__ float r_sh[DD];
    __shared__ float red[4];
    int j = blockIdx.x;
    int u = threadIdx.x;
    r_sh[u] = R[j * DD + u];
    __syncthreads();
    float acc = 0.0f;
    const float* Wp = W + 128 * UU + u;  // W2 rows start at 128
#pragma unroll 8
    for (int k = 0; k < DD; k++) acc += r_sh[k] * Wp[k * UU];
    g_RW2[j * UU + u] = acc;
    // sR[j] = sum_u RW2[j][u] * a[u] + a_b
    float p = acc * a[u];
#pragma unroll
    for (int o = 16; o > 0; o >>= 1) p += __shfl_down_sync(0xffffffffu, p, o);
    if ((u & 31) == 0) red[u >> 5] = p;
    __syncthreads();
    if (u == 0) g_sR[j] = red[0] + red[1] + red[2] + red[3] + a_b[0];
}

// ---------------------------------------------------------------------------
// K4: tensor-core GEMM via mma.sync (bf16 hi/lo split, fp32 accum)
// C[ne x 256] = Eemb[ne x 128] @ [W1 | W3] -> EW1, EW3; epilogue fuses
// sA = EW1 . a and sB = EW3 . a.
// Block: 256 threads (8 warps), tile 128 rows x 256 cols, warp tile 64x64.
#define SSTR 272                       // smem row stride (bytes): bank = 4*row + cb32
#define SA_H 0
#define SA_L 34816                     // 128*272
#define SB_H 69632
#define SB_L 139264                    // SB: 256*272 each
#define SAVEC 208896
#define SDOT  209408                   // 128 rows x 2 floats
#define SM_TOT 210432

__device__ __forceinline__ void split2(float x, float y, unsigned& hi, unsigned& lo) {
    __nv_bfloat16 hx = __float2bfloat16(x), hy = __float2bfloat16(y);
    __nv_bfloat16 lx = __float2bfloat16(x - __bfloat162float(hx));
    __nv_bfloat16 ly = __float2bfloat16(y - __bfloat162float(hy));
    hi = ((unsigned)__bfloat16_as_ushort(hy) << 16) | (unsigned)__bfloat16_as_ushort(hx);
    lo = ((unsigned)__bfloat16_as_ushort(ly) << 16) | (unsigned)__bfloat16_as_ushort(lx);
}

__device__ __forceinline__ void mma16816(float* d, const unsigned* a, const unsigned* b) {
    asm volatile(
        "mma.sync.aligned.m16n8k16.row.col.f32.bf16.bf16.f32 "
        "{%0,%1,%2,%3}, {%4,%5,%6,%7}, {%8,%9}, {%0,%1,%2,%3};"
        : "+f"(d[0]), "+f"(d[1]), "+f"(d[2]), "+f"(d[3])
        : "r"(a[0]), "r"(a[1]), "r"(a[2]), "r"(a[3]), "r"(b[0]), "r"(b[1]));
}

__global__ void __launch_bounds__(256, 1)
k_gemm_mma(const float* __restrict__ Eemb, const float* __restrict__ W,
           const float* __restrict__ a, int ne) {
    extern __shared__ char sm[];
    int tid = threadIdx.x, wid = tid >> 5, lane = tid & 31;
    int warp_m = wid & 1, warp_n = wid >> 1;   // 2 x 4 warp grid (64x64 tiles)
    int row0 = blockIdx.x * 128;

    // a vector + sdot zero
    if (tid < 128) ((float*)(sm + SAVEC))[tid] = a[tid];
    ((float*)(sm + SDOT))[tid] = 0.0f;

    // ---- fill B (W1|W3 transposed): B[u][k], u in [0,256), hi/lo split ----
    // warp handles 8 u x 8 k per iter; lane -> (u0 + (lane>>2), k0 + (lane&3)*2)
    for (int m = wid; m < 512; m += 8) {
        int u0 = (m >> 4) << 3;
        int k0 = (m & 15) << 3;
        int u = u0 + (lane >> 2);
        int k = k0 + (lane & 3) * 2;
        const float* src = (u < 128) ? (W + (size_t)k * UU + u)
                                     : (W + (size_t)(256 + k) * UU + (u - 128));
        float w0 = src[0];
        float w1 = src[UU];
        unsigned hi, lo;
        split2(w0, w1, hi, lo);
        *(unsigned*)(sm + SB_H + u * SSTR + k * 2) = hi;
        *(unsigned*)(sm + SB_L + u * SSTR + k * 2) = lo;
    }

    // ---- fill A tile: 128 rows x 128 k, hi/lo split ----
#pragma unroll
    for (int it = 0; it < 16; it++) {
        int idx = it * 256 + tid;
        int row = idx >> 5, k0 = (idx & 31) * 4;
        float4 v = make_float4(0.f, 0.f, 0.f, 0.f);
        if (row0 + row < ne) v = *(const float4*)(Eemb + (size_t)(row0 + row) * DD + k0);
        unsigned h0, l0, h1, l1;
        split2(v.x, v.y, h0, l0);
        split2(v.z, v.w, h1, l1);
        *(uint2*)(sm + SA_H + row * SSTR + k0 * 2) = make_uint2(h0, h1);
        *(uint2*)(sm + SA_L + row * SSTR + k0 * 2) = make_uint2(l0, l1);
    }
    __syncthreads();

    // ---- mainloop: 8 k-steps, 4 m-frags x 8 n-frags, 3 mma terms ----
    float acc[4][8][4];
#pragma unroll
    for (int i = 0; i < 4; i++)
#pragma unroll
        for (int j = 0; j < 8; j++)
#pragma unroll
            for (int q = 0; q < 4; q++) acc[i][j][q] = 0.f;

    int g = lane >> 2, t4 = lane & 3;
#pragma unroll
    for (int ks = 0; ks < 8; ks++) {
        int kc = ks * 16 + t4 * 2;     // element col for this thread's frag regs
        unsigned ah[4][4], al[4][4];
#pragma unroll
        for (int i = 0; i < 4; i++) {
            int r = warp_m * 64 + i * 16 + g;
            ah[i][0] = *(unsigned*)(sm + SA_H + r * SSTR + kc * 2);
            ah[i][1] = *(unsigned*)(sm + SA_H + (r + 8) * SSTR + kc * 2);
            ah[i][2] = *(unsigned*)(sm + SA_H + r * SSTR + (kc + 8) * 2);
            ah[i][3] = *(unsigned*)(sm + SA_H + (r + 8) * SSTR + (kc + 8) * 2);
            al[i][0] = *(unsigned*)(sm + SA_L + r * SSTR + kc * 2);
            al[i][1] = *(unsigned*)(sm + SA_L + (r + 8) * SSTR + kc * 2);
            al[i][2] = *(unsigned*)(sm + SA_L + r * SSTR + (kc + 8) * 2);
            al[i][3] = *(unsigned*)(sm + SA_L + (r + 8) * SSTR + (kc + 8) * 2);
        }
#pragma unroll
        for (int j = 0; j < 8; j++) {
            int u = warp_n * 64 + j * 8 + g;
            unsigned bh[2], bl[2];
            bh[0] = *(unsigned*)(sm + SB_H + u * SSTR + kc * 2);
            bh[1] = *(unsigned*)(sm + SB_H + u * SSTR + (kc + 8) * 2);
            bl[0] = *(unsigned*)(sm + SB_L + u * SSTR + kc * 2);
            bl[1] = *(unsigned*)(sm + SB_L + u * SSTR + (kc + 8) * 2);
#pragma unroll
            for (int i = 0; i < 4; i++) {
                mma16816(acc[i][j], ah[i], bh);
                mma16816(acc[i][j], al[i], bh);
                mma16816(acc[i][j], ah[i], bl);
            }
        }
    }

    // ---- epilogue: write EW1/EW3, fuse sA/sB dots ----
    const float* av = (const float*)(sm + SAVEC);
    float* sdot = (float*)(sm + SDOT);
    int sel = (warp_n >= 2) ? 1 : 0;   // 0 -> EW1/sA, 1 -> EW3/sB
#pragma unroll
    for (int i = 0; i < 4; i++) {
        int rl0 = warp_m * 64 + i * 16 + g;   // local row (and rl0+8)
        float p0 = 0.f, p1 = 0.f;
#pragma unroll
        for (int j = 0; j < 8; j++) {
            int col = warp_n * 64 + j * 8 + t4 * 2;     // global col in [0,256)
            int c = col & 127;                           // col within EW1/EW3
            float* base = sel ? g_EW3 : g_EW1;
            int row_g0 = row0 + rl0;
            if (row_g0 < ne)
                *(float2*)(base + (size_t)row_g0 * UU + c) =
                    make_float2(acc[i][j][0], acc[i][j][1]);
            int row_g1 = row_g0 + 8;
            if (row_g1 < ne)
                *(float2*)(base + (size_t)row_g1 * UU + c) =
                    make_float2(acc[i][j][2], acc[i][j][3]);
            p0 += acc[i][j][0] * av[c] + acc[i][j][1] * av[c + 1];
            p1 += acc[i][j][2] * av[c] + acc[i][j][3] * av[c + 1];
        }
        // reduce over the 4 lanes sharing a row
        p0 += __shfl_xor_sync(0xffffffffu, p0, 1);
        p0 += __shfl_xor_sync(0xffffffffu, p0, 2);
        p1 += __shfl_xor_sync(0xffffffffu, p1, 1);
        p1 += __shfl_xor_sync(0xffffffffu, p1, 2);
        if (t4 == 0) {
            atomicAdd(&sdot[rl0 * 2 + sel], p0);
            atomicAdd(&sdot[(rl0 + 8) * 2 + sel], p1);
        }
    }
    __syncthreads();
    {
        int row = tid >> 1, s = tid & 1;
        if (row0 + row < ne) {
            if (s == 0) g_sA[row0 + row] = sdot[tid];
            else        g_sB[row0 + row] = sdot[tid];
        }
    }
}

// ---------------------------------------------------------------------------
// K5: per-edge score -> exp -> segment denom
__global__ void k_edge1(const int* __restrict__ h, const int* __restrict__ r,
                        const int* __restrict__ t, int E) {
    int e = blockIdx.x * blockDim.x + threadIdx.x;
    if (e >= E) return;
    float s = g_sA[h[e]] + g_sR[r[e]] + g_sB[t[e]];
    float sc = (s >= 0.f) ? s : 0.04f * s;   // leaky(leaky(x)), alpha=0.2
    float es = expf(sc);
    g_escore[e] = es;
    atomicAdd(&g_denom[h[e]], es);
}

// K6: per-edge aggregate: out[h] += alpha * (RW2[r] + EW3[t])   (warp per edge)
__global__ void k_edge2(const int* __restrict__ h, const int* __restrict__ r,
                        const int* __restrict__ t, float* __restrict__ out, int E) {
    int warp = (blockIdx.x * blockDim.x + threadIdx.x) >> 5;
    int lane = threadIdx.x & 31;
    if (warp >= E) return;
    int hn = h[warp], rn = r[warp], tn = t[warp];
    float alpha = g_escore[warp] / g_denom[hn];
    float4 rv = ((const float4*)(g_RW2 + (size_t)rn * UU))[lane];
    float4 tv = ((const float4*)(g_EW3 + (size_t)tn * UU))[lane];
    float4 val = make_float4(alpha * (rv.x + tv.x), alpha * (rv.y + tv.y),
                             alpha * (rv.z + tv.z), alpha * (rv.w + tv.w));
    atomicAdd(((float4*)(out + (size_t)hn * UU)) + lane, val);
}

// K7: out = relu(out + [denom>0]*EW1 + bias)
__global__ void k_final(float* __restrict__ out, const float* __restrict__ bias, int ne) {
    int idx = blockIdx.x * blockDim.x + threadIdx.x;
    if (idx >= ne * UU) return;
    int n = idx >> 7;
    int u = idx & 127;
    float v = out[idx] + bias[u];
    if (g_denom[n] > 0.f) v += g_EW1[idx];
    out[idx] = fmaxf(v, 0.f);
}

// ---------------------------------------------------------------------------
extern "C" void kernel_launch(void* const* d_in, const int* in_sizes, int n_in,
                              void* d_out, int out_size) {
    const int*   h    = (const int*)d_in[0];
    const int*   r    = (const int*)d_in[1];
    const int*   t    = (const int*)d_in[2];
    const float* Eemb = (const float*)d_in[3];
    const float* Remb = (const float*)d_in[4];
    const float* W    = (const float*)d_in[5];
    const float* a    = (const float*)d_in[6];
    const float* ab   = (const float*)d_in[7];
    const float* bias = (const float*)d_in[8];
    float* out = (float*)d_out;

    int E  = in_sizes[0];
    int ne = in_sizes[3] / DD;
    int nr = in_sizes[4] / DD;
    int ntiles = (ne + 127) / 128;

    cudaFuncSetAttribute(k_gemm_mma, cudaFuncAttributeMaxDynamicSharedMemorySize, SM_TOT);

    k_init     <<<(ne * UU + 255) / 256, 256>>>(out, ne);
    k_rw2      <<<nr, 128>>>(Remb, W, a, ab);
    k_gemm_mma <<<ntiles, 256, SM_TOT>>>(Eemb, W, a, ne);
    k_edge1    <<<(E + 255) / 256, 256>>>(h, r, t, E);
    k_edge2    <<<(E + 7) / 8, 256>>>(h, r, t, out, E);
    k_final    <<<(ne * UU + 255) / 256, 256>>>(out, bias, ne);
}

// round 5
// speedup vs baseline: 1.7182x; 1.2207x over previous
#include <cuda_runtime.h>
#include <cuda_bf16.h>

#define NE_C 100000
#define NR_C 1000
#define DD   128
#define UU   128
#define E_C  500000

// ---------------- scratch (__device__ globals, allocation-free) ----------------
__device__ float g_EW1[NE_C * UU];
__device__ float g_EW3[NE_C * UU];
__device__ float g_RW2[NR_C * UU];
__device__ float g_sA[NE_C];
__device__ float g_sB[NE_C];
__device__ float g_sR[NR_C];
__device__ int   g_cnt[NE_C];
__device__ int   g_off[NE_C + 1];
__device__ int   g_cur[NE_C];
__device__ int   g_csum[128];
__device__ int   g_rs[E_C];
__device__ int   g_ts[E_C];

// ---------------------------------------------------------------------------
// K2: RW2[j,:] = R[j,:] @ W2 ; sR[j] = RW2[j,:] . a + a_b   (block per relation)
__global__ void k_rw2(const float* __restrict__ R, const float* __restrict__ W,
                      const float* __restrict__ a, const float* __restrict__ a_b) {
    __shared__ float r_sh[DD];
    __shared__ float red[4];
    int j = blockIdx.x;
    int u = threadIdx.x;
    r_sh[u] = R[j * DD + u];
    __syncthreads();
    float acc = 0.0f;
    const float* Wp = W + 128 * UU + u;  // W2 rows start at 128
#pragma unroll 8
    for (int k = 0; k < DD; k++) acc += r_sh[k] * Wp[k * UU];
    g_RW2[j * UU + u] = acc;
    float p = acc * a[u];
#pragma unroll
    for (int o = 16; o > 0; o >>= 1) p += __shfl_down_sync(0xffffffffu, p, o);
    if ((u & 31) == 0) red[u >> 5] = p;
    __syncthreads();
    if (u == 0) g_sR[j] = red[0] + red[1] + red[2] + red[3] + a_b[0];
}

// ---------------------------------------------------------------------------
// K4: tensor-core GEMM via mma.sync (bf16 hi/lo split, fp32 accum)
#define SSTR 272
#define SA_H 0
#define SA_L 34816
#define SB_H 69632
#define SB_L 139264
#define SAVEC 208896
#define SDOT  209408
#define SM_TOT 210432

__device__ __forceinline__ void split2(float x, float y, unsigned& hi, unsigned& lo) {
    __nv_bfloat16 hx = __float2bfloat16(x), hy = __float2bfloat16(y);
    __nv_bfloat16 lx = __float2bfloat16(x - __bfloat162float(hx));
    __nv_bfloat16 ly = __float2bfloat16(y - __bfloat162float(hy));
    hi = ((unsigned)__bfloat16_as_ushort(hy) << 16) | (unsigned)__bfloat16_as_ushort(hx);
    lo = ((unsigned)__bfloat16_as_ushort(ly) << 16) | (unsigned)__bfloat16_as_ushort(lx);
}

__device__ __forceinline__ void mma16816(float* d, const unsigned* a, const unsigned* b) {
    asm volatile(
        "mma.sync.aligned.m16n8k16.row.col.f32.bf16.bf16.f32 "
        "{%0,%1,%2,%3}, {%4,%5,%6,%7}, {%8,%9}, {%0,%1,%2,%3};"
        : "+f"(d[0]), "+f"(d[1]), "+f"(d[2]), "+f"(d[3])
        : "r"(a[0]), "r"(a[1]), "r"(a[2]), "r"(a[3]), "r"(b[0]), "r"(b[1]));
}

__global__ void __launch_bounds__(256, 1)
k_gemm_mma(const float* __restrict__ Eemb, const float* __restrict__ W,
           const float* __restrict__ a, int ne) {
    extern __shared__ char sm[];
    int tid = threadIdx.x, wid = tid >> 5, lane = tid & 31;
    int warp_m = wid & 1, warp_n = wid >> 1;
    int row0 = blockIdx.x * 128;

    if (tid < 128) ((float*)(sm + SAVEC))[tid] = a[tid];
    ((float*)(sm + SDOT))[tid] = 0.0f;

    for (int m = wid; m < 512; m += 8) {
        int u0 = (m >> 4) << 3;
        int k0 = (m & 15) << 3;
        int u = u0 + (lane >> 2);
        int k = k0 + (lane & 3) * 2;
        const float* src = (u < 128) ? (W + (size_t)k * UU + u)
                                     : (W + (size_t)(256 + k) * UU + (u - 128));
        float w0 = src[0];
        float w1 = src[UU];
        unsigned hi, lo;
        split2(w0, w1, hi, lo);
        *(unsigned*)(sm + SB_H + u * SSTR + k * 2) = hi;
        *(unsigned*)(sm + SB_L + u * SSTR + k * 2) = lo;
    }

#pragma unroll
    for (int it = 0; it < 16; it++) {
        int idx = it * 256 + tid;
        int row = idx >> 5, k0 = (idx & 31) * 4;
        float4 v = make_float4(0.f, 0.f, 0.f, 0.f);
        if (row0 + row < ne) v = *(const float4*)(Eemb + (size_t)(row0 + row) * DD + k0);
        unsigned h0, l0, h1, l1;
        split2(v.x, v.y, h0, l0);
        split2(v.z, v.w, h1, l1);
        *(uint2*)(sm + SA_H + row * SSTR + k0 * 2) = make_uint2(h0, h1);
        *(uint2*)(sm + SA_L + row * SSTR + k0 * 2) = make_uint2(l0, l1);
    }
    __syncthreads();

    float acc[4][8][4];
#pragma unroll
    for (int i = 0; i < 4; i++)
#pragma unroll
        for (int j = 0; j < 8; j++)
#pragma unroll
            for (int q = 0; q < 4; q++) acc[i][j][q] = 0.f;

    int g = lane >> 2, t4 = lane & 3;
#pragma unroll
    for (int ks = 0; ks < 8; ks++) {
        int kc = ks * 16 + t4 * 2;
        unsigned ah[4][4], al[4][4];
#pragma unroll
        for (int i = 0; i < 4; i++) {
            int r = warp_m * 64 + i * 16 + g;
            ah[i][0] = *(unsigned*)(sm + SA_H + r * SSTR + kc * 2);
            ah[i][1] = *(unsigned*)(sm + SA_H + (r + 8) * SSTR + kc * 2);
            ah[i][2] = *(unsigned*)(sm + SA_H + r * SSTR + (kc + 8) * 2);
            ah[i][3] = *(unsigned*)(sm + SA_H + (r + 8) * SSTR + (kc + 8) * 2);
            al[i][0] = *(unsigned*)(sm + SA_L + r * SSTR + kc * 2);
            al[i][1] = *(unsigned*)(sm + SA_L + (r + 8) * SSTR + kc * 2);
            al[i][2] = *(unsigned*)(sm + SA_L + r * SSTR + (kc + 8) * 2);
            al[i][3] = *(unsigned*)(sm + SA_L + (r + 8) * SSTR + (kc + 8) * 2);
        }
#pragma unroll
        for (int j = 0; j < 8; j++) {
            int u = warp_n * 64 + j * 8 + g;
            unsigned bh[2], bl[2];
            bh[0] = *(unsigned*)(sm + SB_H + u * SSTR + kc * 2);
            bh[1] = *(unsigned*)(sm + SB_H + u * SSTR + (kc + 8) * 2);
            bl[0] = *(unsigned*)(sm + SB_L + u * SSTR + kc * 2);
            bl[1] = *(unsigned*)(sm + SB_L + u * SSTR + (kc + 8) * 2);
#pragma unroll
            for (int i = 0; i < 4; i++) {
                mma16816(acc[i][j], ah[i], bh);
                mma16816(acc[i][j], al[i], bh);
                mma16816(acc[i][j], ah[i], bl);
            }
        }
    }

    const float* av = (const float*)(sm + SAVEC);
    float* sdot = (float*)(sm + SDOT);
    int sel = (warp_n >= 2) ? 1 : 0;
#pragma unroll
    for (int i = 0; i < 4; i++) {
        int rl0 = warp_m * 64 + i * 16 + g;
        float p0 = 0.f, p1 = 0.f;
#pragma unroll
        for (int j = 0; j < 8; j++) {
            int col = warp_n * 64 + j * 8 + t4 * 2;
            int c = col & 127;
            float* base = sel ? g_EW3 : g_EW1;
            int row_g0 = row0 + rl0;
            if (row_g0 < ne)
                *(float2*)(base + (size_t)row_g0 * UU + c) =
                    make_float2(acc[i][j][0], acc[i][j][1]);
            int row_g1 = row_g0 + 8;
            if (row_g1 < ne)
                *(float2*)(base + (size_t)row_g1 * UU + c) =
                    make_float2(acc[i][j][2], acc[i][j][3]);
            p0 += acc[i][j][0] * av[c] + acc[i][j][1] * av[c + 1];
            p1 += acc[i][j][2] * av[c] + acc[i][j][3] * av[c + 1];
        }
        p0 += __shfl_xor_sync(0xffffffffu, p0, 1);
        p0 += __shfl_xor_sync(0xffffffffu, p0, 2);
        p1 += __shfl_xor_sync(0xffffffffu, p1, 1);
        p1 += __shfl_xor_sync(0xffffffffu, p1, 2);
        if (t4 == 0) {
            atomicAdd(&sdot[rl0 * 2 + sel], p0);
            atomicAdd(&sdot[(rl0 + 8) * 2 + sel], p1);
        }
    }
    __syncthreads();
    {
        int row = tid >> 1, s = tid & 1;
        if (row0 + row < ne) {
            if (s == 0) g_sA[row0 + row] = sdot[tid];
            else        g_sB[row0 + row] = sdot[tid];
        }
    }
}

// ---------------------------------------------------------------------------
// Counting sort of edges by h
__global__ void k_zero_cnt(int ne) {
    int i = blockIdx.x * blockDim.x + threadIdx.x;
    if (i < ne) g_cnt[i] = 0;
}
__global__ void k_hist(const int* __restrict__ h, int E) {
    int e = blockIdx.x * blockDim.x + threadIdx.x;
    if (e < E) atomicAdd(&g_cnt[h[e]], 1);
}
// scanA: per-chunk (1024) exclusive scan; chunk sums to g_csum
__global__ void k_scanA(int ne) {
    __shared__ int warp_s[8];
    int tid = threadIdx.x;
    int base = blockIdx.x * 1024;
    int lane = tid & 31, w = tid >> 5;
    int v[4], s = 0;
#pragma unroll
    for (int i = 0; i < 4; i++) {
        int idx = base + tid * 4 + i;
        v[i] = (idx < ne) ? g_cnt[idx] : 0;
        s += v[i];
    }
    int x = s;
#pragma unroll
    for (int o = 1; o < 32; o <<= 1) {
        int y = __shfl_up_sync(0xffffffffu, x, o);
        if (lane >= o) x += y;
    }
    if (lane == 31) warp_s[w] = x;
    __syncthreads();
    if (w == 0) {
        int ws = (lane < 8) ? warp_s[lane] : 0;
#pragma unroll
        for (int o = 1; o < 8; o <<= 1) {
            int y = __shfl_up_sync(0xffffffffu, ws, o);
            if (lane >= o) ws += y;
        }
        if (lane < 8) warp_s[lane] = ws;
    }
    __syncthreads();
    int excl = x - s + (w > 0 ? warp_s[w - 1] : 0);
    int run = excl;
#pragma unroll
    for (int i = 0; i < 4; i++) {
        int idx = base + tid * 4 + i;
        if (idx < ne) g_off[idx] = run;
        run += v[i];
    }
    if (tid == 0) g_csum[blockIdx.x] = warp_s[7];
}
// scanB: single block, exclusive scan of chunk sums (<=128 chunks)
__global__ void k_scanB(int nch) {
    __shared__ int warp_s[4];
    int tid = threadIdx.x, lane = tid & 31, w = tid >> 5;
    int v = (tid < nch) ? g_csum[tid] : 0;
    int x = v;
#pragma unroll
    for (int o = 1; o < 32; o <<= 1) {
        int y = __shfl_up_sync(0xffffffffu, x, o);
        if (lane >= o) x += y;
    }
    if (lane == 31) warp_s[w] = x;
    __syncthreads();
    if (w == 0 && lane < 4) {
        int ws = warp_s[lane];
#pragma unroll
        for (int o = 1; o < 4; o <<= 1) {
            int y = __shfl_up_sync(0x0000000fu, ws, o);
            if (lane >= o) ws += y;
        }
        warp_s[lane] = ws;
    }
    __syncthreads();
    int excl = x - v + (w > 0 ? warp_s[w - 1] : 0);
    if (tid < nch) g_csum[tid] = excl;
}
// scanC: add chunk base, init cursor, set off[ne]=E
__global__ void k_scanC(int ne, int E) {
    int i = blockIdx.x * blockDim.x + threadIdx.x;
    if (i < ne) {
        int o = g_off[i] + g_csum[i >> 10];
        g_off[i] = o;
        g_cur[i] = o;
    }
    if (i == 0) g_off[ne] = E;
}
__global__ void k_scatter(const int* __restrict__ h, const int* __restrict__ r,
                          const int* __restrict__ t, int E) {
    int e = blockIdx.x * blockDim.x + threadIdx.x;
    if (e >= E) return;
    int pos = atomicAdd(&g_cur[h[e]], 1);
    g_rs[pos] = r[e];
    g_ts[pos] = t[e];
}

// ---------------------------------------------------------------------------
// Aggregation: warp per node. out[n] = relu( sum_e alpha_e*(RW2+EW3) + EW1[n] + bias )
__global__ void __launch_bounds__(256)
k_agg(float* __restrict__ out, const float* __restrict__ bias, int ne) {
    int warp = (blockIdx.x * blockDim.x + threadIdx.x) >> 5;
    int lane = threadIdx.x & 31;
    if (warp >= ne) return;
    int start = g_off[warp], end = g_off[warp + 1];
    float sAn = g_sA[warp];

    // denom
    float denom = 0.f;
    for (int e = start + lane; e < end; e += 32) {
        float s = sAn + g_sR[g_rs[e]] + g_sB[g_ts[e]];
        float sc = (s >= 0.f) ? s : 0.04f * s;
        denom += expf(sc);
    }
#pragma unroll
    for (int o = 16; o > 0; o >>= 1) denom += __shfl_xor_sync(0xffffffffu, denom, o);

    // un-normalized accumulation
    float4 acc = make_float4(0.f, 0.f, 0.f, 0.f);
    for (int e = start; e < end; e++) {
        int rn = g_rs[e], tn = g_ts[e];
        float s = sAn + g_sR[rn] + g_sB[tn];
        float sc = (s >= 0.f) ? s : 0.04f * s;
        float es = expf(sc);
        float4 rv = ((const float4*)(g_RW2 + (size_t)rn * UU))[lane];
        float4 tv = ((const float4*)(g_EW3 + (size_t)tn * UU))[lane];
        acc.x += es * (rv.x + tv.x);
        acc.y += es * (rv.y + tv.y);
        acc.z += es * (rv.z + tv.z);
        acc.w += es * (rv.w + tv.w);
    }

    float4 bv = ((const float4*)bias)[lane];
    float4 o;
    if (end > start) {
        float inv = 1.f / denom;
        float4 ew = ((const float4*)(g_EW1 + (size_t)warp * UU))[lane];
        o = make_float4(acc.x * inv + ew.x + bv.x, acc.y * inv + ew.y + bv.y,
                        acc.z * inv + ew.z + bv.z, acc.w * inv + ew.w + bv.w);
    } else {
        o = bv;
    }
    o.x = fmaxf(o.x, 0.f); o.y = fmaxf(o.y, 0.f);
    o.z = fmaxf(o.z, 0.f); o.w = fmaxf(o.w, 0.f);
    ((float4*)(out + (size_t)warp * UU))[lane] = o;
}

// ---------------------------------------------------------------------------
extern "C" void kernel_launch(void* const* d_in, const int* in_sizes, int n_in,
                              void* d_out, int out_size) {
    const int*   h    = (const int*)d_in[0];
    const int*   r    = (const int*)d_in[1];
    const int*   t    = (const int*)d_in[2];
    const float* Eemb = (const float*)d_in[3];
    const float* Remb = (const float*)d_in[4];
    const float* W    = (const float*)d_in[5];
    const float* a    = (const float*)d_in[6];
    const float* ab   = (const float*)d_in[7];
    const float* bias = (const float*)d_in[8];
    float* out = (float*)d_out;

    int E  = in_sizes[0];
    int ne = in_sizes[3] / DD;
    int nr = in_sizes[4] / DD;
    int ntiles = (ne + 127) / 128;
    int nchunks = (ne + 1023) / 1024;

    cudaFuncSetAttribute(k_gemm_mma, cudaFuncAttributeMaxDynamicSharedMemorySize, SM_TOT);

    k_zero_cnt <<<(ne + 255) / 256, 256>>>(ne);
    k_rw2      <<<nr, 128>>>(Remb, W, a, ab);
    k_gemm_mma <<<ntiles, 256, SM_TOT>>>(Eemb, W, a, ne);
    k_hist     <<<(E + 255) / 256, 256>>>(h, E);
    k_scanA    <<<nchunks, 256>>>(ne);
    k_scanB    <<<1, 128>>>(nchunks);
    k_scanC    <<<(ne + 255) / 256, 256>>>(ne, E);
    k_scatter  <<<(E + 255) / 256, 256>>>(h, r, t, E);
    k_agg      <<<(ne + 7) / 8, 256>>>(out, bias, ne);
}

// round 6
// speedup vs baseline: 2.0912x; 1.2170x over previous
#include <cuda_runtime.h>
#include <cuda_bf16.h>

#define NE_C 100000
#define NR_C 1000
#define DD   128
#define UU   128
#define E_C  500000

// ---------------- scratch (__device__ globals, allocation-free) ----------------
__device__ float g_EW1[NE_C * UU];
__device__ float g_EW3[NE_C * UU];
__device__ float g_RW2[NR_C * UU];
__device__ float g_sA[NE_C];
__device__ float g_sB[NE_C];
__device__ float g_sR[NR_C];
__device__ int   g_cnt[NE_C];
__device__ int   g_off[NE_C + 1];
__device__ int   g_cur[NE_C];
__device__ int   g_csum[128];
__device__ int   g_rs[E_C];
__device__ int   g_ts[E_C];
// precomputed bf16 hi/lo split of [W1|W3] transposed: dense [u][k], u<256, k<128
__device__ unsigned short g_Bh[256 * 128];
__device__ unsigned short g_Bl[256 * 128];

// ---------------------------------------------------------------------------
__device__ __forceinline__ void split1(float x, unsigned short& hi, unsigned short& lo) {
    __nv_bfloat16 hx = __float2bfloat16(x);
    __nv_bfloat16 lx = __float2bfloat16(x - __bfloat162float(hx));
    hi = __bfloat16_as_ushort(hx);
    lo = __bfloat16_as_ushort(lx);
}
__device__ __forceinline__ void split2(float x, float y, unsigned& hi, unsigned& lo) {
    __nv_bfloat16 hx = __float2bfloat16(x), hy = __float2bfloat16(y);
    __nv_bfloat16 lx = __float2bfloat16(x - __bfloat162float(hx));
    __nv_bfloat16 ly = __float2bfloat16(y - __bfloat162float(hy));
    hi = ((unsigned)__bfloat16_as_ushort(hy) << 16) | (unsigned)__bfloat16_as_ushort(hx);
    lo = ((unsigned)__bfloat16_as_ushort(ly) << 16) | (unsigned)__bfloat16_as_ushort(lx);
}

// K1: one-time W split. thread -> (half, k, u4); coalesced float4 reads of W rows.
__global__ void k_wsplit(const float* __restrict__ W) {
    int id = blockIdx.x * blockDim.x + threadIdx.x;   // 8192 threads
    int half = id >> 12;
    int rem = id & 4095;
    int k = rem >> 5;
    int u4 = (rem & 31) * 4;
    const float* src = W + (size_t)(half ? (256 + k) : k) * UU + u4;
    float4 v = *(const float4*)src;
    int ubase = half * 128 + u4;
    unsigned short h, l;
    split1(v.x, h, l); g_Bh[(ubase + 0) * 128 + k] = h; g_Bl[(ubase + 0) * 128 + k] = l;
    split1(v.y, h, l); g_Bh[(ubase + 1) * 128 + k] = h; g_Bl[(ubase + 1) * 128 + k] = l;
    split1(v.z, h, l); g_Bh[(ubase + 2) * 128 + k] = h; g_Bl[(ubase + 2) * 128 + k] = l;
    split1(v.w, h, l); g_Bh[(ubase + 3) * 128 + k] = h; g_Bl[(ubase + 3) * 128 + k] = l;
}

// K2: RW2[j,:] = R[j,:] @ W2 ; sR[j] = RW2[j,:] . a + a_b   (block per relation)
__global__ void k_rw2(const float* __restrict__ R, const float* __restrict__ W,
                      const float* __restrict__ a, const float* __restrict__ a_b) {
    __shared__ float r_sh[DD];
    __shared__ float red[4];
    int j = blockIdx.x;
    int u = threadIdx.x;
    r_sh[u] = R[j * DD + u];
    __syncthreads();
    float acc = 0.0f;
    const float* Wp = W + 128 * UU + u;  // W2 rows start at 128
#pragma unroll 8
    for (int k = 0; k < DD; k++) acc += r_sh[k] * Wp[k * UU];
    g_RW2[j * UU + u] = acc;
    float p = acc * a[u];
#pragma unroll
    for (int o = 16; o > 0; o >>= 1) p += __shfl_down_sync(0xffffffffu, p, o);
    if ((u & 31) == 0) red[u >> 5] = p;
    __syncthreads();
    if (u == 0) g_sR[j] = red[0] + red[1] + red[2] + red[3] + a_b[0];
}

// ---------------------------------------------------------------------------
// K4: persistent tensor-core GEMM via mma.sync (bf16 hi/lo split, fp32 accum)
#define SSTR 272
#define SA_H 0
#define SA_L 34816
#define SB_H 69632
#define SB_L 139264
#define SAVEC 208896
#define SDOT  209408
#define SM_TOT 210432

__device__ __forceinline__ void mma16816(float* d, const unsigned* a, const unsigned* b) {
    asm volatile(
        "mma.sync.aligned.m16n8k16.row.col.f32.bf16.bf16.f32 "
        "{%0,%1,%2,%3}, {%4,%5,%6,%7}, {%8,%9}, {%0,%1,%2,%3};"
        : "+f"(d[0]), "+f"(d[1]), "+f"(d[2]), "+f"(d[3])
        : "r"(a[0]), "r"(a[1]), "r"(a[2]), "r"(a[3]), "r"(b[0]), "r"(b[1]));
}

__global__ void __launch_bounds__(256, 1)
k_gemm_mma(const float* __restrict__ Eemb, const float* __restrict__ a,
           int ne, int ntiles) {
    extern __shared__ char sm[];
    int tid = threadIdx.x, wid = tid >> 5, lane = tid & 31;
    int warp_m = wid & 1, warp_n = wid >> 1;
    int g = lane >> 2, t4 = lane & 3;

    if (tid < 128) ((float*)(sm + SAVEC))[tid] = a[tid];

    // ---- fill B once: coalesced uint4 copy from precomputed split ----
    // 256 rows x 16 uint4 per half = 4096 uint4; 16 per thread
#pragma unroll
    for (int it = 0; it < 16; it++) {
        int idx = it * 256 + tid;
        int u = idx >> 4, c = idx & 15;         // c: which 16B chunk (8 k's)
        uint4 vh = ((const uint4*)g_Bh)[idx];
        uint4 vl = ((const uint4*)g_Bl)[idx];
        *(uint4*)(sm + SB_H + u * SSTR + c * 16) = vh;
        *(uint4*)(sm + SB_L + u * SSTR + c * 16) = vl;
    }
    __syncthreads();

    const float* av = (const float*)(sm + SAVEC);
    float* sdot = (float*)(sm + SDOT);

    for (int tile = blockIdx.x; tile < ntiles; tile += gridDim.x) {
        int row0 = tile * 128;
        sdot[tid] = 0.0f;

        // ---- fill A tile (128 rows x 128 k), split ----
#pragma unroll
        for (int it = 0; it < 16; it++) {
            int idx = it * 256 + tid;
            int row = idx >> 5, k0 = (idx & 31) * 4;
            float4 v = make_float4(0.f, 0.f, 0.f, 0.f);
            if (row0 + row < ne) v = *(const float4*)(Eemb + (size_t)(row0 + row) * DD + k0);
            unsigned h0, l0, h1, l1;
            split2(v.x, v.y, h0, l0);
            split2(v.z, v.w, h1, l1);
            *(uint2*)(sm + SA_H + row * SSTR + k0 * 2) = make_uint2(h0, h1);
            *(uint2*)(sm + SA_L + row * SSTR + k0 * 2) = make_uint2(l0, l1);
        }
        __syncthreads();

        // ---- mainloop ----
        float acc[4][8][4];
#pragma unroll
        for (int i = 0; i < 4; i++)
#pragma unroll
            for (int j = 0; j < 8; j++)
#pragma unroll
                for (int q = 0; q < 4; q++) acc[i][j][q] = 0.f;

#pragma unroll
        for (int ks = 0; ks < 8; ks++) {
            int kc = ks * 16 + t4 * 2;
            unsigned ah[4][4], al[4][4];
#pragma unroll
            for (int i = 0; i < 4; i++) {
                int r = warp_m * 64 + i * 16 + g;
                ah[i][0] = *(unsigned*)(sm + SA_H + r * SSTR + kc * 2);
                ah[i][1] = *(unsigned*)(sm + SA_H + (r + 8) * SSTR + kc * 2);
                ah[i][2] = *(unsigned*)(sm + SA_H + r * SSTR + (kc + 8) * 2);
                ah[i][3] = *(unsigned*)(sm + SA_H + (r + 8) * SSTR + (kc + 8) * 2);
                al[i][0] = *(unsigned*)(sm + SA_L + r * SSTR + kc * 2);
                al[i][1] = *(unsigned*)(sm + SA_L + (r + 8) * SSTR + kc * 2);
                al[i][2] = *(unsigned*)(sm + SA_L + r * SSTR + (kc + 8) * 2);
                al[i][3] = *(unsigned*)(sm + SA_L + (r + 8) * SSTR + (kc + 8) * 2);
            }
#pragma unroll
            for (int j = 0; j < 8; j++) {
                int u = warp_n * 64 + j * 8 + g;
                unsigned bh[2], bl[2];
                bh[0] = *(unsigned*)(sm + SB_H + u * SSTR + kc * 2);
                bh[1] = *(unsigned*)(sm + SB_H + u * SSTR + (kc + 8) * 2);
                bl[0] = *(unsigned*)(sm + SB_L + u * SSTR + kc * 2);
                bl[1] = *(unsigned*)(sm + SB_L + u * SSTR + (kc + 8) * 2);
#pragma unroll
                for (int i = 0; i < 4; i++) {
                    mma16816(acc[i][j], ah[i], bh);
                    mma16816(acc[i][j], al[i], bh);
                    mma16816(acc[i][j], ah[i], bl);
                }
            }
        }

        // ---- epilogue ----
        int sel = (warp_n >= 2) ? 1 : 0;
#pragma unroll
        for (int i = 0; i < 4; i++) {
            int rl0 = warp_m * 64 + i * 16 + g;
            float p0 = 0.f, p1 = 0.f;
#pragma unroll
            for (int j = 0; j < 8; j++) {
                int col = warp_n * 64 + j * 8 + t4 * 2;
                int c = col & 127;
                float* base = sel ? g_EW3 : g_EW1;
                int row_g0 = row0 + rl0;
                if (row_g0 < ne)
                    *(float2*)(base + (size_t)row_g0 * UU + c) =
                        make_float2(acc[i][j][0], acc[i][j][1]);
                int row_g1 = row_g0 + 8;
                if (row_g1 < ne)
                    *(float2*)(base + (size_t)row_g1 * UU + c) =
                        make_float2(acc[i][j][2], acc[i][j][3]);
                p0 += acc[i][j][0] * av[c] + acc[i][j][1] * av[c + 1];
                p1 += acc[i][j][2] * av[c] + acc[i][j][3] * av[c + 1];
            }
            p0 += __shfl_xor_sync(0xffffffffu, p0, 1);
            p0 += __shfl_xor_sync(0xffffffffu, p0, 2);
            p1 += __shfl_xor_sync(0xffffffffu, p1, 1);
            p1 += __shfl_xor_sync(0xffffffffu, p1, 2);
            if (t4 == 0) {
                atomicAdd(&sdot[rl0 * 2 + sel], p0);
                atomicAdd(&sdot[(rl0 + 8) * 2 + sel], p1);
            }
        }
        __syncthreads();
        {
            int row = tid >> 1, s = tid & 1;
            if (row0 + row < ne) {
                if (s == 0) g_sA[row0 + row] = sdot[tid];
                else        g_sB[row0 + row] = sdot[tid];
            }
        }
        __syncthreads();   // protect sdot/SA before next tile overwrites
    }
}

// ---------------------------------------------------------------------------
// Counting sort of edges by h
__global__ void k_zero_cnt(int ne) {
    int i = blockIdx.x * blockDim.x + threadIdx.x;
    if (i < ne) g_cnt[i] = 0;
}
__global__ void k_hist(const int* __restrict__ h, int E) {
    int e = blockIdx.x * blockDim.x + threadIdx.x;
    if (e < E) atomicAdd(&g_cnt[h[e]], 1);
}
__global__ void k_scanA(int ne) {
    __shared__ int warp_s[8];
    int tid = threadIdx.x;
    int base = blockIdx.x * 1024;
    int lane = tid & 31, w = tid >> 5;
    int v[4], s = 0;
#pragma unroll
    for (int i = 0; i < 4; i++) {
        int idx = base + tid * 4 + i;
        v[i] = (idx < ne) ? g_cnt[idx] : 0;
        s += v[i];
    }
    int x = s;
#pragma unroll
    for (int o = 1; o < 32; o <<= 1) {
        int y = __shfl_up_sync(0xffffffffu, x, o);
        if (lane >= o) x += y;
    }
    if (lane == 31) warp_s[w] = x;
    __syncthreads();
    if (w == 0) {
        int ws = (lane < 8) ? warp_s[lane] : 0;
#pragma unroll
        for (int o = 1; o < 8; o <<= 1) {
            int y = __shfl_up_sync(0xffffffffu, ws, o);
            if (lane >= o) ws += y;
        }
        if (lane < 8) warp_s[lane] = ws;
    }
    __syncthreads();
    int excl = x - s + (w > 0 ? warp_s[w - 1] : 0);
    int run = excl;
#pragma unroll
    for (int i = 0; i < 4; i++) {
        int idx = base + tid * 4 + i;
        if (idx < ne) g_off[idx] = run;
        run += v[i];
    }
    if (tid == 0) g_csum[blockIdx.x] = warp_s[7];
}
__global__ void k_scanB(int nch) {
    __shared__ int warp_s[4];
    int tid = threadIdx.x, lane = tid & 31, w = tid >> 5;
    int v = (tid < nch) ? g_csum[tid] : 0;
    int x = v;
#pragma unroll
    for (int o = 1; o < 32; o <<= 1) {
        int y = __shfl_up_sync(0xffffffffu, x, o);
        if (lane >= o) x += y;
    }
    if (lane == 31) warp_s[w] = x;
    __syncthreads();
    if (w == 0 && lane < 4) {
        int ws = warp_s[lane];
#pragma unroll
        for (int o = 1; o < 4; o <<= 1) {
            int y = __shfl_up_sync(0x0000000fu, ws, o);
            if (lane >= o) ws += y;
        }
        warp_s[lane] = ws;
    }
    __syncthreads();
    int excl = x - v + (w > 0 ? warp_s[w - 1] : 0);
    if (tid < nch) g_csum[tid] = excl;
}
__global__ void k_scanC(int ne, int E) {
    int i = blockIdx.x * blockDim.x + threadIdx.x;
    if (i < ne) {
        int o = g_off[i] + g_csum[i >> 10];
        g_off[i] = o;
        g_cur[i] = o;
    }
    if (i == 0) g_off[ne] = E;
}
__global__ void k_scatter(const int* __restrict__ h, const int* __restrict__ r,
                          const int* __restrict__ t, int E) {
    int e = blockIdx.x * blockDim.x + threadIdx.x;
    if (e >= E) return;
    int pos = atomicAdd(&g_cur[h[e]], 1);
    g_rs[pos] = r[e];
    g_ts[pos] = t[e];
}

// ---------------------------------------------------------------------------
// Aggregation: warp per node, single fused pass.
__global__ void __launch_bounds__(256)
k_agg(float* __restrict__ out, const float* __restrict__ bias, int ne) {
    int warp = (blockIdx.x * blockDim.x + threadIdx.x) >> 5;
    int lane = threadIdx.x & 31;
    if (warp >= ne) return;
    int start = g_off[warp], end = g_off[warp + 1];
    float4 bv = ((const float4*)bias)[lane];
    float4 o;
    if (end > start) {
        float sAn = g_sA[warp];
        float denom = 0.f;
        float4 acc = make_float4(0.f, 0.f, 0.f, 0.f);
#pragma unroll 2
        for (int e = start; e < end; e++) {
            int rn = g_rs[e], tn = g_ts[e];
            float s = sAn + g_sR[rn] + g_sB[tn];
            float sc = (s >= 0.f) ? s : 0.04f * s;
            float es = __expf(sc);
            denom += es;
            float4 rv = ((const float4*)(g_RW2 + (size_t)rn * UU))[lane];
            float4 tv = ((const float4*)(g_EW3 + (size_t)tn * UU))[lane];
            acc.x += es * (rv.x + tv.x);
            acc.y += es * (rv.y + tv.y);
            acc.z += es * (rv.z + tv.z);
            acc.w += es * (rv.w + tv.w);
        }
        float inv = 1.f / denom;
        float4 ew = ((const float4*)(g_EW1 + (size_t)warp * UU))[lane];
        o = make_float4(acc.x * inv + ew.x + bv.x, acc.y * inv + ew.y + bv.y,
                        acc.z * inv + ew.z + bv.z, acc.w * inv + ew.w + bv.w);
    } else {
        o = bv;
    }
    o.x = fmaxf(o.x, 0.f); o.y = fmaxf(o.y, 0.f);
    o.z = fmaxf(o.z, 0.f); o.w = fmaxf(o.w, 0.f);
    ((float4*)(out + (size_t)warp * UU))[lane] = o;
}

// ---------------------------------------------------------------------------
extern "C" void kernel_launch(void* const* d_in, const int* in_sizes, int n_in,
                              void* d_out, int out_size) {
    const int*   h    = (const int*)d_in[0];
    const int*   r    = (const int*)d_in[1];
    const int*   t    = (const int*)d_in[2];
    const float* Eemb = (const float*)d_in[3];
    const float* Remb = (const float*)d_in[4];
    const float* W    = (const float*)d_in[5];
    const float* a    = (const float*)d_in[6];
    const float* ab   = (const float*)d_in[7];
    const float* bias = (const float*)d_in[8];
    float* out = (float*)d_out;

    int E  = in_sizes[0];
    int ne = in_sizes[3] / DD;
    int nr = in_sizes[4] / DD;
    int ntiles = (ne + 127) / 128;
    int nchunks = (ne + 1023) / 1024;

    cudaFuncSetAttribute(k_gemm_mma, cudaFuncAttributeMaxDynamicSharedMemorySize, SM_TOT);

    k_zero_cnt <<<(ne + 255) / 256, 256>>>(ne);
    k_wsplit   <<<32, 256>>>(W);
    k_rw2      <<<nr, 128>>>(Remb, W, a, ab);
    k_gemm_mma <<<148, 256, SM_TOT>>>(Eemb, a, ne, ntiles);
    k_hist     <<<(E + 255) / 256, 256>>>(h, E);
    k_scanA    <<<nchunks, 256>>>(ne);
    k_scanB    <<<1, 128>>>(nchunks);
    k_scanC    <<<(ne + 255) / 256, 256>>>(ne, E);
    k_scatter  <<<(E + 255) / 256, 256>>>(h, r, t, E);
    k_agg      <<<(ne + 7) / 8, 256>>>(out, bias, ne);
}

// round 7
// speedup vs baseline: 2.1420x; 1.0243x over previous
#include <cuda_runtime.h>
#include <cuda_bf16.h>

#define NE_C 100000
#define NR_C 1000
#define DD   128
#define UU   128
#define E_C  500000
#define GRID_GEMM 152

// ---------------- scratch (__device__ globals, allocation-free) ----------------
__device__ float g_EW1[NE_C * UU];
__device__ float g_EW3[NE_C * UU];
__device__ float g_RW2[NR_C * UU];
__device__ float g_sA[NE_C];
__device__ float g_sB[NE_C];
__device__ float g_sR[NR_C];
__device__ int   g_cnt[NE_C];
__device__ int   g_off[NE_C + 1];
__device__ int   g_cur[NE_C];
__device__ int   g_csum[128];
__device__ int   g_rs[E_C];
__device__ int   g_ts[E_C];
// precomputed bf16 hi/lo split of [W1|W3] transposed: dense [u][k], u<256, k<128
__device__ unsigned short g_Bh[256 * 128];
__device__ unsigned short g_Bl[256 * 128];

// ---------------------------------------------------------------------------
__device__ __forceinline__ void split1(float x, unsigned short& hi, unsigned short& lo) {
    __nv_bfloat16 hx = __float2bfloat16(x);
    __nv_bfloat16 lx = __float2bfloat16(x - __bfloat162float(hx));
    hi = __bfloat16_as_ushort(hx);
    lo = __bfloat16_as_ushort(lx);
}
__device__ __forceinline__ void split2(float x, float y, unsigned& hi, unsigned& lo) {
    __nv_bfloat16 hx = __float2bfloat16(x), hy = __float2bfloat16(y);
    __nv_bfloat16 lx = __float2bfloat16(x - __bfloat162float(hx));
    __nv_bfloat16 ly = __float2bfloat16(y - __bfloat162float(hy));
    hi = ((unsigned)__bfloat16_as_ushort(hy) << 16) | (unsigned)__bfloat16_as_ushort(hx);
    lo = ((unsigned)__bfloat16_as_ushort(ly) << 16) | (unsigned)__bfloat16_as_ushort(lx);
}

__device__ __forceinline__ unsigned smem_u32(const void* p) {
    unsigned a;
    asm("{ .reg .u64 t; cvta.to.shared.u64 t, %1; cvt.u32.u64 %0, t; }" : "=r"(a) : "l"(p));
    return a;
}
#define CP_ASYNC16(dst, src) \
    asm volatile("cp.async.cg.shared.global [%0], [%1], 16;" :: "r"(dst), "l"(src))
#define CP_COMMIT() asm volatile("cp.async.commit_group;")
#define CP_WAIT0()  asm volatile("cp.async.wait_group 0;" ::: "memory")

// K1: fused prep: zero cnt + one-time W split (coalesced)
__global__ void k_prep(const float* __restrict__ W, int ne) {
    int id = blockIdx.x * blockDim.x + threadIdx.x;
    if (id < ne) g_cnt[id] = 0;
    if (id < 8192) {
        int half = id >> 12;
        int rem = id & 4095;
        int k = rem >> 5;
        int u4 = (rem & 31) * 4;
        const float* src = W + (size_t)(half ? (256 + k) : k) * UU + u4;
        float4 v = *(const float4*)src;
        int ubase = half * 128 + u4;
        unsigned short h, l;
        split1(v.x, h, l); g_Bh[(ubase + 0) * 128 + k] = h; g_Bl[(ubase + 0) * 128 + k] = l;
        split1(v.y, h, l); g_Bh[(ubase + 1) * 128 + k] = h; g_Bl[(ubase + 1) * 128 + k] = l;
        split1(v.z, h, l); g_Bh[(ubase + 2) * 128 + k] = h; g_Bl[(ubase + 2) * 128 + k] = l;
        split1(v.w, h, l); g_Bh[(ubase + 3) * 128 + k] = h; g_Bl[(ubase + 3) * 128 + k] = l;
    }
}

// K2: RW2[j,:] = R[j,:] @ W2 ; sR[j] = RW2[j,:] . a + a_b   (block per relation)
__global__ void k_rw2(const float* __restrict__ R, const float* __restrict__ W,
                      const float* __restrict__ a, const float* __restrict__ a_b) {
    __shared__ float r_sh[DD];
    __shared__ float red[4];
    int j = blockIdx.x;
    int u = threadIdx.x;
    r_sh[u] = R[j * DD + u];
    __syncthreads();
    float acc = 0.0f;
    const float* Wp = W + 128 * UU + u;
#pragma unroll 8
    for (int k = 0; k < DD; k++) acc += r_sh[k] * Wp[k * UU];
    g_RW2[j * UU + u] = acc;
    float p = acc * a[u];
#pragma unroll
    for (int o = 16; o > 0; o >>= 1) p += __shfl_down_sync(0xffffffffu, p, o);
    if ((u & 31) == 0) red[u >> 5] = p;
    __syncthreads();
    if (u == 0) g_sR[j] = red[0] + red[1] + red[2] + red[3] + a_b[0];
}

// ---------------------------------------------------------------------------
// K4: persistent pipelined tensor-core GEMM (bf16 hi/lo split, fp32 accum)
// Work unit = (half, tile): half 0 -> EW1/sA (cols 0..127 of W1), half 1 -> EW3/sB.
// cp.async stages raw fp32 A tiles; next tile's stage overlaps current mainloop.
#define SSTR  272
#define SA_H  0
#define SA_L  34816
#define SB_H  69632
#define SB_L  104448
#define SSTG  139264                 // fp32 stage: 128 rows x 512B
#define SAVEC 204800
#define SDOT  205312
#define SM_TOT 205824

__device__ __forceinline__ void mma16816(float* d, const unsigned* a, const unsigned* b) {
    asm volatile(
        "mma.sync.aligned.m16n8k16.row.col.f32.bf16.bf16.f32 "
        "{%0,%1,%2,%3}, {%4,%5,%6,%7}, {%8,%9}, {%0,%1,%2,%3};"
        : "+f"(d[0]), "+f"(d[1]), "+f"(d[2]), "+f"(d[3])
        : "r"(a[0]), "r"(a[1]), "r"(a[2]), "r"(a[3]), "r"(b[0]), "r"(b[1]));
}

__global__ void __launch_bounds__(256, 1)
k_gemm_mma(const float* __restrict__ Eemb, const float* __restrict__ a,
           int ne, int ntiles) {
    extern __shared__ char sm[];
    unsigned smb = smem_u32(sm);
    int tid = threadIdx.x, wid = tid >> 5, lane = tid & 31;
    int warp_m = wid & 1, warp_n = wid >> 1;   // 2 m-warps x 4 n-warps (64x32 warp tile)
    int g = lane >> 2, t4 = lane & 3;
    int nunits = ntiles * 2;

    if (tid < 128) ((float*)(sm + SAVEC))[tid] = a[tid];

    // issue stage for first unit's tile
    {
        int u0 = blockIdx.x;
        if (u0 < nunits) {
            int tile = (u0 >= ntiles) ? (u0 - ntiles) : u0;
            int row0 = tile * 128;
#pragma unroll
            for (int it = 0; it < 16; it++) {
                int row = it * 8 + wid;
                unsigned dst = smb + SSTG + row * 512 + lane * 16;
                if (row0 + row < ne)
                    CP_ASYNC16(dst, Eemb + (size_t)(row0 + row) * DD + lane * 4);
                else
                    *(float4*)(sm + SSTG + row * 512 + lane * 16) =
                        make_float4(0.f, 0.f, 0.f, 0.f);
            }
        }
        CP_COMMIT();
    }

    const float* av = (const float*)(sm + SAVEC);
    float* sdot = (float*)(sm + SDOT);
    int cur_half = -1;

    for (int u = blockIdx.x; u < nunits; u += GRID_GEMM) {
        int half = (u >= ntiles) ? 1 : 0;
        int tile = u - half * ntiles;
        int row0 = tile * 128;

        if (half != cur_half) {
            // fill B for this half (coalesced from precomputed split)
#pragma unroll
            for (int it = 0; it < 8; it++) {
                int idx = it * 256 + tid;       // 2048 uint4
                int ur = idx >> 4, c = idx & 15;
                uint4 vh = ((const uint4*)g_Bh)[(half * 128 + ur) * 16 + c];
                uint4 vl = ((const uint4*)g_Bl)[(half * 128 + ur) * 16 + c];
                *(uint4*)(sm + SB_H + ur * SSTR + c * 16) = vh;
                *(uint4*)(sm + SB_L + ur * SSTR + c * 16) = vl;
            }
            cur_half = half;
            __syncthreads();
        }

        // wait for stage, convert to bf16 hi/lo (per-thread mapping == copy mapping)
        CP_WAIT0();
#pragma unroll
        for (int it = 0; it < 16; it++) {
            int row = it * 8 + wid;
            float4 v = *(const float4*)(sm + SSTG + row * 512 + lane * 16);
            unsigned h0, l0, h1, l1;
            split2(v.x, v.y, h0, l0);
            split2(v.z, v.w, h1, l1);
            *(uint2*)(sm + SA_H + row * SSTR + lane * 8) = make_uint2(h0, h1);
            *(uint2*)(sm + SA_L + row * SSTR + lane * 8) = make_uint2(l0, l1);
        }
        __syncthreads();
        if (tid < 128) sdot[tid] = 0.0f;

        // issue stage for next unit (overlaps mainloop + epilogue)
        {
            int nu = u + GRID_GEMM;
            if (nu < nunits) {
                int ntile = (nu >= ntiles) ? (nu - ntiles) : nu;
                int nrow0 = ntile * 128;
#pragma unroll
                for (int it = 0; it < 16; it++) {
                    int row = it * 8 + wid;
                    unsigned dst = smb + SSTG + row * 512 + lane * 16;
                    if (nrow0 + row < ne)
                        CP_ASYNC16(dst, Eemb + (size_t)(nrow0 + row) * DD + lane * 4);
                    else
                        *(float4*)(sm + SSTG + row * 512 + lane * 16) =
                            make_float4(0.f, 0.f, 0.f, 0.f);
                }
            }
            CP_COMMIT();
        }

        // ---- mainloop: warp tile 64x32, 8 k-steps, 3 mma terms ----
        float acc[4][4][4];
#pragma unroll
        for (int i = 0; i < 4; i++)
#pragma unroll
            for (int j = 0; j < 4; j++)
#pragma unroll
                for (int q = 0; q < 4; q++) acc[i][j][q] = 0.f;

#pragma unroll
        for (int ks = 0; ks < 8; ks++) {
            int kc = ks * 16 + t4 * 2;
            unsigned ah[4][4], al[4][4];
#pragma unroll
            for (int i = 0; i < 4; i++) {
                int r = warp_m * 64 + i * 16 + g;
                ah[i][0] = *(unsigned*)(sm + SA_H + r * SSTR + kc * 2);
                ah[i][1] = *(unsigned*)(sm + SA_H + (r + 8) * SSTR + kc * 2);
                ah[i][2] = *(unsigned*)(sm + SA_H + r * SSTR + (kc + 8) * 2);
                ah[i][3] = *(unsigned*)(sm + SA_H + (r + 8) * SSTR + (kc + 8) * 2);
                al[i][0] = *(unsigned*)(sm + SA_L + r * SSTR + kc * 2);
                al[i][1] = *(unsigned*)(sm + SA_L + (r + 8) * SSTR + kc * 2);
                al[i][2] = *(unsigned*)(sm + SA_L + r * SSTR + (kc + 8) * 2);
                al[i][3] = *(unsigned*)(sm + SA_L + (r + 8) * SSTR + (kc + 8) * 2);
            }
#pragma unroll
            for (int j = 0; j < 4; j++) {
                int ur = warp_n * 32 + j * 8 + g;
                unsigned bh[2], bl[2];
                bh[0] = *(unsigned*)(sm + SB_H + ur * SSTR + kc * 2);
                bh[1] = *(unsigned*)(sm + SB_H + ur * SSTR + (kc + 8) * 2);
                bl[0] = *(unsigned*)(sm + SB_L + ur * SSTR + kc * 2);
                bl[1] = *(unsigned*)(sm + SB_L + ur * SSTR + (kc + 8) * 2);
#pragma unroll
                for (int i = 0; i < 4; i++) {
                    mma16816(acc[i][j], ah[i], bh);
                    mma16816(acc[i][j], al[i], bh);
                    mma16816(acc[i][j], ah[i], bl);
                }
            }
        }

        // ---- epilogue: write EW half, fused dot with a ----
        float* base = half ? g_EW3 : g_EW1;
#pragma unroll
        for (int i = 0; i < 4; i++) {
            int rl0 = warp_m * 64 + i * 16 + g;
            float p0 = 0.f, p1 = 0.f;
#pragma unroll
            for (int j = 0; j < 4; j++) {
                int c = warp_n * 32 + j * 8 + t4 * 2;
                int row_g0 = row0 + rl0;
                if (row_g0 < ne)
                    *(float2*)(base + (size_t)row_g0 * UU + c) =
                        make_float2(acc[i][j][0], acc[i][j][1]);
                int row_g1 = row_g0 + 8;
                if (row_g1 < ne)
                    *(float2*)(base + (size_t)row_g1 * UU + c) =
                        make_float2(acc[i][j][2], acc[i][j][3]);
                p0 += acc[i][j][0] * av[c] + acc[i][j][1] * av[c + 1];
                p1 += acc[i][j][2] * av[c] + acc[i][j][3] * av[c + 1];
            }
            p0 += __shfl_xor_sync(0xffffffffu, p0, 1);
            p0 += __shfl_xor_sync(0xffffffffu, p0, 2);
            p1 += __shfl_xor_sync(0xffffffffu, p1, 1);
            p1 += __shfl_xor_sync(0xffffffffu, p1, 2);
            if (t4 == 0) {
                atomicAdd(&sdot[rl0], p0);
                atomicAdd(&sdot[rl0 + 8], p1);
            }
        }
        __syncthreads();
        if (tid < 128 && row0 + tid < ne) {
            if (half) g_sB[row0 + tid] = sdot[tid];
            else      g_sA[row0 + tid] = sdot[tid];
        }
        __syncthreads();
    }
}

// ---------------------------------------------------------------------------
// Counting sort of edges by h
__global__ void k_hist(const int* __restrict__ h, int E) {
    int e = blockIdx.x * blockDim.x + threadIdx.x;
    if (e < E) atomicAdd(&g_cnt[h[e]], 1);
}
__global__ void k_scanA(int ne) {
    __shared__ int warp_s[8];
    int tid = threadIdx.x;
    int base = blockIdx.x * 1024;
    int lane = tid & 31, w = tid >> 5;
    int v[4], s = 0;
#pragma unroll
    for (int i = 0; i < 4; i++) {
        int idx = base + tid * 4 + i;
        v[i] = (idx < ne) ? g_cnt[idx] : 0;
        s += v[i];
    }
    int x = s;
#pragma unroll
    for (int o = 1; o < 32; o <<= 1) {
        int y = __shfl_up_sync(0xffffffffu, x, o);
        if (lane >= o) x += y;
    }
    if (lane == 31) warp_s[w] = x;
    __syncthreads();
    if (w == 0) {
        int ws = (lane < 8) ? warp_s[lane] : 0;
#pragma unroll
        for (int o = 1; o < 8; o <<= 1) {
            int y = __shfl_up_sync(0xffffffffu, ws, o);
            if (lane >= o) ws += y;
        }
        if (lane < 8) warp_s[lane] = ws;
    }
    __syncthreads();
    int excl = x - s + (w > 0 ? warp_s[w - 1] : 0);
    int run = excl;
#pragma unroll
    for (int i = 0; i < 4; i++) {
        int idx = base + tid * 4 + i;
        if (idx < ne) g_off[idx] = run;
        run += v[i];
    }
    if (tid == 0) g_csum[blockIdx.x] = warp_s[7];
}
__global__ void k_scanB(int nch) {
    __shared__ int warp_s[4];
    int tid = threadIdx.x, lane = tid & 31, w = tid >> 5;
    int v = (tid < nch) ? g_csum[tid] : 0;
    int x = v;
#pragma unroll
    for (int o = 1; o < 32; o <<= 1) {
        int y = __shfl_up_sync(0xffffffffu, x, o);
        if (lane >= o) x += y;
    }
    if (lane == 31) warp_s[w] = x;
    __syncthreads();
    if (w == 0 && lane < 4) {
        int ws = warp_s[lane];
#pragma unroll
        for (int o = 1; o < 4; o <<= 1) {
            int y = __shfl_up_sync(0x0000000fu, ws, o);
            if (lane >= o) ws += y;
        }
        warp_s[lane] = ws;
    }
    __syncthreads();
    int excl = x - v + (w > 0 ? warp_s[w - 1] : 0);
    if (tid < nch) g_csum[tid] = excl;
}
__global__ void k_scanC(int ne, int E) {
    int i = blockIdx.x * blockDim.x + threadIdx.x;
    if (i < ne) {
        int o = g_off[i] + g_csum[i >> 10];
        g_off[i] = o;
        g_cur[i] = o;
    }
    if (i == 0) g_off[ne] = E;
}
__global__ void k_scatter(const int* __restrict__ h, const int* __restrict__ r,
                          const int* __restrict__ t, int E) {
    int e = blockIdx.x * blockDim.x + threadIdx.x;
    if (e >= E) return;
    int pos = atomicAdd(&g_cur[h[e]], 1);
    g_rs[pos] = r[e];
    g_ts[pos] = t[e];
}

// ---------------------------------------------------------------------------
// Aggregation: warp per node, single fused pass.
__global__ void __launch_bounds__(256)
k_agg(float* __restrict__ out, const float* __restrict__ bias, int ne) {
    int warp = (blockIdx.x * blockDim.x + threadIdx.x) >> 5;
    int lane = threadIdx.x & 31;
    if (warp >= ne) return;
    int start = g_off[warp], end = g_off[warp + 1];
    float4 bv = ((const float4*)bias)[lane];
    float4 o;
    if (end > start) {
        float sAn = g_sA[warp];
        float denom = 0.f;
        float4 acc = make_float4(0.f, 0.f, 0.f, 0.f);
#pragma unroll 2
        for (int e = start; e < end; e++) {
            int rn = g_rs[e], tn = g_ts[e];
            float s = sAn + g_sR[rn] + g_sB[tn];
            float sc = (s >= 0.f) ? s : 0.04f * s;
            float es = __expf(sc);
            denom += es;
            float4 rv = ((const float4*)(g_RW2 + (size_t)rn * UU))[lane];
            float4 tv = ((const float4*)(g_EW3 + (size_t)tn * UU))[lane];
            acc.x += es * (rv.x + tv.x);
            acc.y += es * (rv.y + tv.y);
            acc.z += es * (rv.z + tv.z);
            acc.w += es * (rv.w + tv.w);
        }
        float inv = 1.f / denom;
        float4 ew = ((const float4*)(g_EW1 + (size_t)warp * UU))[lane];
        o = make_float4(acc.x * inv + ew.x + bv.x, acc.y * inv + ew.y + bv.y,
                        acc.z * inv + ew.z + bv.z, acc.w * inv + ew.w + bv.w);
    } else {
        o = bv;
    }
    o.x = fmaxf(o.x, 0.f); o.y = fmaxf(o.y, 0.f);
    o.z = fmaxf(o.z, 0.f); o.w = fmaxf(o.w, 0.f);
    ((float4*)(out + (size_t)warp * UU))[lane] = o;
}

// ---------------------------------------------------------------------------
extern "C" void kernel_launch(void* const* d_in, const int* in_sizes, int n_in,
                              void* d_out, int out_size) {
    const int*   h    = (const int*)d_in[0];
    const int*   r    = (const int*)d_in[1];
    const int*   t    = (const int*)d_in[2];
    const float* Eemb = (const float*)d_in[3];
    const float* Remb = (const float*)d_in[4];
    const float* W    = (const float*)d_in[5];
    const float* a    = (const float*)d_in[6];
    const float* ab   = (const float*)d_in[7];
    const float* bias = (const float*)d_in[8];
    float* out = (float*)d_out;

    int E  = in_sizes[0];
    int ne = in_sizes[3] / DD;
    int nr = in_sizes[4] / DD;
    int ntiles = (ne + 127) / 128;
    int nchunks = (ne + 1023) / 1024;

    cudaFuncSetAttribute(k_gemm_mma, cudaFuncAttributeMaxDynamicSharedMemorySize, SM_TOT);

    k_prep     <<<(ne + 255) / 256, 256>>>(W, ne);
    k_rw2      <<<nr, 128>>>(Remb, W, a, ab);
    k_gemm_mma <<<GRID_GEMM, 256, SM_TOT>>>(Eemb, a, ne, ntiles);
    k_hist     <<<(E + 255) / 256, 256>>>(h, E);
    k_scanA    <<<nchunks, 256>>>(ne);
    k_scanB    <<<1, 128>>>(nchunks);
    k_scanC    <<<(ne + 255) / 256, 256>>>(ne, E);
    k_scatter  <<<(E + 255) / 256, 256>>>(h, r, t, E);
    k_agg      <<<(ne + 7) / 8, 256>>>(out, bias, ne);
}